// round 2
// baseline (speedup 1.0000x reference)
#include <cuda_runtime.h>

#define NN 262144              // total nodes
#define NE 2097152             // total edges
#define NG 1024                // graphs
#define NPG 256                // nodes per graph
#define MAXDEG 64              // per-node in-edge capacity (avg deg 8)

// ---------------- scratch (static device memory; no runtime allocation) ----
__device__ int            g_is64;
__device__ int            g_cur[NN];                      // in-degree / fill cursor
__device__ unsigned char  g_col[(size_t)NN * MAXDEG];     // 16MB: local src ids (0..255)
__device__ float          g_dinv[NN];
__device__ float          g_h1[(size_t)NN * 32];          // 32MB
__device__ float          g_h2[(size_t)NN * 64];          // 64MB
__device__ float          g_ctx[NG * 64];                 // per-graph mean pool
__device__ float          g_ctxB[NG * 64];                // ctx @ fc1_W[64:] + fc1_b

// ---------------- dtype-agnostic index loads --------------------------------
__device__ __forceinline__ int edge_val(const void* ei, long long idx, int is64) {
    if (is64) return (int)((const long long*)ei)[idx];
    return ((const int*)ei)[idx];
}

// edge_index may be int32 or int64 depending on jax x64 config.
// If int64 (little-endian), every odd 32-bit word of the first 1024 values is 0
// (all node ids < 2^18). For int32 those words are random node ids.
__global__ void k_detect(const unsigned int* ei) {
    bool ok = true;
    for (int i = threadIdx.x; i < 1024; i += 32)
        if (ei[2 * i + 1] != 0u) ok = false;
    unsigned m = __ballot_sync(0xffffffffu, ok);
    if (threadIdx.x == 0) g_is64 = (m == 0xffffffffu) ? 1 : 0;
}

__global__ void k_zero() {
    int i = blockIdx.x * blockDim.x + threadIdx.x;
    if (i < NN) g_cur[i] = 0;
}

// single pass: build capped CSR; g_cur ends as the exact in-degree
__global__ void k_fill(const void* ei) {
    int e = blockIdx.x * blockDim.x + threadIdx.x;
    if (e < NE) {
        int is64 = g_is64;
        int s = edge_val(ei, e, is64);
        int d = edge_val(ei, (long long)NE + e, is64);
        int pos = atomicAdd(&g_cur[d], 1);
        if (pos < MAXDEG)
            g_col[(size_t)d * MAXDEG + pos] = (unsigned char)(s & 255);
    }
}

__global__ void k_dinv() {
    int i = blockIdx.x * blockDim.x + threadIdx.x;
    if (i < NN) g_dinv[i] = rsqrtf((float)g_cur[i] + 1.0f);
}

// ---------------- Layer 1: fused (X@W1)·dinv -> SMEM gather-agg -> ReLU -----
// block = one graph (256 threads, 8 warps)
__global__ void __launch_bounds__(256) k_layer1(const float* __restrict__ x,
                                                const float* __restrict__ W1,
                                                const float* __restrict__ b1) {
    __shared__ float xs[256 * 9];
    __shared__ float W1s[9 * 32];
    __shared__ float b1s[32];
    __shared__ float dv[256];
    __shared__ float p1[256 * 33];   // pad 33: conflict-free both phases

    int g = blockIdx.x, t = threadIdx.x;
    int base = g * NPG;

    for (int i = t; i < 256 * 9; i += 256) xs[i] = x[(size_t)base * 9 + i];
    for (int i = t; i < 288; i += 256) W1s[i] = W1[i];      // FIXED: full 288 loaded
    if (t < 32)  b1s[t] = b1[t];
    dv[t] = g_dinv[base + t];
    __syncthreads();

    // linear: p1[i][c] = dinv[i] * sum_k x[i][k] * W1[k][c]
    {
        float di = dv[t];
        #pragma unroll
        for (int c0 = 0; c0 < 32; c0 += 4) {
            float a0 = 0.f, a1 = 0.f, a2 = 0.f, a3 = 0.f;
            #pragma unroll
            for (int k = 0; k < 9; k++) {
                float a = xs[t * 9 + k];
                float4 w = *(const float4*)&W1s[k * 32 + c0];
                a0 += a * w.x; a1 += a * w.y; a2 += a * w.z; a3 += a * w.w;
            }
            p1[t * 33 + c0 + 0] = di * a0;
            p1[t * 33 + c0 + 1] = di * a1;
            p1[t * 33 + c0 + 2] = di * a2;
            p1[t * 33 + c0 + 3] = di * a3;
        }
    }
    __syncthreads();

    // aggregate: warp per node, lane = channel
    int w = t >> 5, lane = t & 31;
    for (int n = w; n < 256; n += 8) {
        int node = base + n;
        int kn = min(g_cur[node], MAXDEG);
        const unsigned char* cp = &g_col[(size_t)node * MAXDEG];
        float s = 0.f;
        for (int k = 0; k < kn; k++) {
            int j = cp[k];
            s += p1[j * 33 + lane];
        }
        float h = dv[n] * (s + p1[n * 33 + lane]) + b1s[lane];
        g_h1[(size_t)node * 32 + lane] = fmaxf(h, 0.f);
    }
}

// ---------------- Layer 2: fused (H1@W2)·dinv -> agg -> ReLU -> mean pool ---
extern __shared__ float sm2[];
__global__ void __launch_bounds__(256) k_layer2(const float* __restrict__ W2,
                                                const float* __restrict__ b2) {
    float* h1s  = sm2;                  // 256*33
    float* W2s  = h1s + 256 * 33;       // 2048
    float* dv   = W2s + 2048;           // 256
    float* b2s  = dv + 256;             // 64
    float* pool = b2s + 64;             // 8*64
    float* p2   = pool + 512;           // 256*66 (even pad -> aligned float2)

    int g = blockIdx.x, t = threadIdx.x;
    int base = g * NPG;

    for (int i = t; i < 256 * 32; i += 256)
        h1s[(i >> 5) * 33 + (i & 31)] = g_h1[(size_t)base * 32 + i];
    for (int i = t; i < 2048; i += 256) W2s[i] = W2[i];
    if (t < 64) b2s[t] = b2[t];
    dv[t] = g_dinv[base + t];
    __syncthreads();

    // linear: p2[i][c] = dinv[i] * sum_k h1[i][k] * W2[k][c]
    {
        float a[32];
        #pragma unroll
        for (int k = 0; k < 32; k++) a[k] = h1s[t * 33 + k];
        float di = dv[t];
        #pragma unroll
        for (int c0 = 0; c0 < 64; c0 += 4) {
            float a0 = 0.f, a1 = 0.f, a2 = 0.f, a3 = 0.f;
            #pragma unroll
            for (int k = 0; k < 32; k++) {
                float4 w = *(const float4*)&W2s[k * 64 + c0];
                a0 += a[k] * w.x; a1 += a[k] * w.y;
                a2 += a[k] * w.z; a3 += a[k] * w.w;
            }
            p2[t * 66 + c0 + 0] = di * a0;
            p2[t * 66 + c0 + 1] = di * a1;
            p2[t * 66 + c0 + 2] = di * a2;
            p2[t * 66 + c0 + 3] = di * a3;
        }
    }
    __syncthreads();

    // aggregate: warp per node, lane = channel pair (2l, 2l+1); fused pooling
    int w = t >> 5, lane = t & 31;
    int c0 = 2 * lane, c1 = 2 * lane + 1;
    float pl0 = 0.f, pl1 = 0.f;
    for (int n = w; n < 256; n += 8) {
        int node = base + n;
        int kn = min(g_cur[node], MAXDEG);
        const unsigned char* cp = &g_col[(size_t)node * MAXDEG];
        float s0 = 0.f, s1 = 0.f;
        for (int k = 0; k < kn; k++) {
            int j = cp[k];
            float2 v = *(const float2*)&p2[j * 66 + c0];
            s0 += v.x; s1 += v.y;
        }
        float2 ps = *(const float2*)&p2[n * 66 + c0];
        float h0 = dv[n] * (s0 + ps.x) + b2s[c0];
        float h1v = dv[n] * (s1 + ps.y) + b2s[c1];
        h0 = fmaxf(h0, 0.f); h1v = fmaxf(h1v, 0.f);
        float2 o; o.x = h0; o.y = h1v;
        *(float2*)&g_h2[(size_t)node * 64 + c0] = o;
        pl0 += h0; pl1 += h1v;
    }
    pool[w * 64 + c0] = pl0;
    pool[w * 64 + c1] = pl1;
    __syncthreads();
    if (w == 0) {
        float s0 = 0.f, s1 = 0.f;
        #pragma unroll
        for (int ww = 0; ww < 8; ww++) { s0 += pool[ww * 64 + c0]; s1 += pool[ww * 64 + c1]; }
        g_ctx[g * 64 + c0] = s0 * (1.f / 256.f);
        g_ctx[g * 64 + c1] = s1 * (1.f / 256.f);
    }
}

// ---------------- ctxB = ctx @ fc1_W[64:128] + fc1_b (per graph, shared) ----
__global__ void k_ctxB(const float* __restrict__ fc1W, const float* __restrict__ fc1b) {
    int id = blockIdx.x * blockDim.x + threadIdx.x;
    if (id < NG * 64) {
        int g = id >> 6, c = id & 63;
        float s = fc1b[c];
        const float* cx = &g_ctx[g * 64];
        #pragma unroll
        for (int k = 0; k < 64; k++) s += cx[k] * fc1W[(64 + k) * 64 + c];
        g_ctxB[id] = s;
    }
}

// ---------------- head: warp per (graph, station) ---------------------------
__global__ void __launch_bounds__(256) k_final(const float* __restrict__ fc1W,
                                               const float* __restrict__ fc2W,
                                               const float* __restrict__ fc2b,
                                               const void* __restrict__ sids,
                                               float* __restrict__ out) {
    __shared__ float As[64 * 64];    // fc1_W rows [0:64] (station-emb part)
    __shared__ float ctxBs[64];
    __shared__ float f2[64];
    __shared__ int   sid[8];

    int g = blockIdx.x, t = threadIdx.x;
    for (int i = t; i < 4096; i += 256) As[i] = fc1W[i];
    if (t < 64) { ctxBs[t] = g_ctxB[g * 64 + t]; f2[t] = fc2W[t]; }
    if (t < 8) {
        sid[t] = g_is64 ? (int)((const long long*)sids)[t]
                        : ((const int*)sids)[t];
    }
    __syncthreads();

    int w = t >> 5, lane = t & 31;
    int node = g * 256 + sid[w];
    float e0 = g_h2[(size_t)node * 64 + lane];
    float e1 = g_h2[(size_t)node * 64 + 32 + lane];
    float h0 = ctxBs[lane], h1v = ctxBs[lane + 32];
    #pragma unroll
    for (int k = 0; k < 64; k++) {
        float ek = __shfl_sync(0xffffffffu, (k < 32) ? e0 : e1, k & 31);
        h0  += ek * As[k * 64 + lane];
        h1v += ek * As[k * 64 + lane + 32];
    }
    h0 = fmaxf(h0, 0.f); h1v = fmaxf(h1v, 0.f);
    float q = h0 * f2[lane] + h1v * f2[lane + 32];
    #pragma unroll
    for (int off = 16; off; off >>= 1)
        q += __shfl_down_sync(0xffffffffu, q, off);
    if (lane == 0) out[g * 8 + w] = q + fc2b[0];
}

// ---------------------------------------------------------------------------
extern "C" void kernel_launch(void* const* d_in, const int* in_sizes, int n_in,
                              void* d_out, int out_size) {
    // Map inputs by element count (robust to metadata ordering conventions).
    // Unique sizes: x=2359296, edge_index=4194304, station_ids=8, W1=288,
    // b1=32, W2=2048, fc1_W=8192, fc2_b=1. The three size-64 arrays appear
    // in order (b2, fc1_b, fc2_W) under both insertion and alphabetical order.
    const float *x = 0, *W1 = 0, *b1 = 0, *W2 = 0, *fc1W = 0, *fc2b = 0;
    const void  *ei = 0, *sids = 0;
    const float *sz64[3] = {0, 0, 0};
    int n64 = 0;
    for (int i = 0; i < n_in; i++) {
        switch (in_sizes[i]) {
            case 2359296: x    = (const float*)d_in[i]; break;
            case 4194304: ei   = d_in[i];               break;
            case 8:       sids = d_in[i];               break;
            case 288:     W1   = (const float*)d_in[i]; break;
            case 32:      b1   = (const float*)d_in[i]; break;
            case 2048:    W2   = (const float*)d_in[i]; break;
            case 8192:    fc1W = (const float*)d_in[i]; break;
            case 1:       fc2b = (const float*)d_in[i]; break;
            case 64:      if (n64 < 3) sz64[n64++] = (const float*)d_in[i]; break;
            default: break;
        }
    }
    const float* b2   = sz64[0];
    const float* fc1b = sz64[1];
    const float* fc2W = sz64[2];
    float* out = (float*)d_out;

    const int SMEM2 = (256 * 33 + 2048 + 256 + 64 + 512 + 256 * 66) * (int)sizeof(float);
    cudaFuncSetAttribute(k_layer2, cudaFuncAttributeMaxDynamicSharedMemorySize, SMEM2);

    k_detect<<<1, 32>>>((const unsigned int*)ei);
    k_zero<<<NN / 256, 256>>>();
    k_fill<<<NE / 256, 256>>>(ei);
    k_dinv<<<NN / 256, 256>>>();
    k_layer1<<<NG, 256>>>(x, W1, b1);
    k_layer2<<<NG, 256, SMEM2>>>(W2, b2);
    k_ctxB<<<(NG * 64 + 255) / 256, 256>>>(fc1W, fc1b);
    k_final<<<NG, 256>>>(fc1W, fc2W, fc2b, sids, out);
}

// round 3
// speedup vs baseline: 1.3176x; 1.3176x over previous
#include <cuda_runtime.h>

#define NN 262144              // total nodes
#define NE 2097152             // total edges
#define NG 1024                // graphs
#define NPG 256                // nodes per graph
#define MAXDEG 64              // per-node in-edge capacity (avg deg 8, tail ~1e-36)

// ---------------- scratch (static device memory) ----------------------------
__device__ int            g_is64;
__device__ int            g_cur[NN];                      // in-degree / fill cursor
__device__ unsigned char  g_col[(size_t)NN * MAXDEG];     // 16MB: local src ids

// ---------------- packed f32x2 helpers (Blackwell) --------------------------
#define FMA2(d, a, b, c) asm("fma.rn.f32x2 %0, %1, %2, %3;" : "=l"(d) : "l"(a), "l"(b), "l"(c))
#define MUL2(d, a, b)    asm("mul.rn.f32x2 %0, %1, %2;"     : "=l"(d) : "l"(a), "l"(b))
#define PACK1(d, s)      asm("mov.b64 %0, {%1, %1};"        : "=l"(d) : "r"(s))

// ---------------- dtype-agnostic index loads --------------------------------
__device__ __forceinline__ int edge_val(const void* ei, long long idx, int is64) {
    if (is64) return (int)((const long long*)ei)[idx];
    return ((const int*)ei)[idx];
}

// edge_index may be int32 or int64. If int64 (LE), every odd 32-bit word of
// the first 1024 values is 0 (node ids < 2^18); for int32 they are node ids.
__global__ void k_detect(const unsigned int* ei) {
    bool ok = true;
    for (int i = threadIdx.x; i < 1024; i += 32)
        if (ei[2 * i + 1] != 0u) ok = false;
    unsigned m = __ballot_sync(0xffffffffu, ok);
    if (threadIdx.x == 0) g_is64 = (m == 0xffffffffu) ? 1 : 0;
}

__global__ void k_zero() {
    int i = blockIdx.x * blockDim.x + threadIdx.x;
    if (i < NN) g_cur[i] = 0;
}

// single pass: build capped CSR; g_cur ends as the exact in-degree
__global__ void k_fill(const void* ei) {
    int e = blockIdx.x * blockDim.x + threadIdx.x;
    if (e < NE) {
        int is64 = g_is64;
        int s = edge_val(ei, e, is64);
        int d = edge_val(ei, (long long)NE + e, is64);
        int pos = atomicAdd(&g_cur[d], 1);
        if (pos < MAXDEG)
            g_col[(size_t)d * MAXDEG + pos] = (unsigned char)(s & 255);
    }
}

// ---------------- fully fused per-graph network ------------------------------
// block = one graph, 512 threads (16 warps). All activations live in SMEM.
// SMEM carve (floats unless noted):
//   p2   [256*66] = 16896     (layer-2 pre-agg; aliases p1 [256*33] in phase 1)
//   h1s  [256*33] =  8448
//   W2s  [2048], As [4096] (fc1_W rows 0..63), xs [2304], pool [16*64=1024]
//   W1s[288] b1s[32] b2s[64] dv[256] ctx[64] ctxB[64] h2st[512] f2[64]
//   knS[256]i stSl[256]i sidS[8]i   colS[16384] uchar (16B aligned)
// total = 146720 + 16384 = 163104 bytes
#define SMEM_FUSED 163104

extern __shared__ float sm[];
__global__ void __launch_bounds__(512) k_fused(
    const float* __restrict__ x,    const float* __restrict__ W1,
    const float* __restrict__ b1,   const float* __restrict__ W2,
    const float* __restrict__ b2,   const float* __restrict__ fc1W,
    const float* __restrict__ fc1b, const float* __restrict__ fc2W,
    const float* __restrict__ fc2b, const void*  __restrict__ sids,
    float* __restrict__ out)
{
    float* p2   = sm;                 // 16896
    float* h1s  = p2 + 16896;         // 8448
    float* W2s  = h1s + 8448;         // 2048
    float* As   = W2s + 2048;         // 4096
    float* xs   = As + 4096;          // 2304
    float* pool = xs + 2304;          // 1024
    float* W1s  = pool + 1024;        // 288
    float* b1s  = W1s + 288;          // 32
    float* b2s  = b1s + 32;           // 64
    float* dv   = b2s + 64;           // 256
    float* ctx  = dv + 256;           // 64
    float* ctxB = ctx + 64;           // 64
    float* h2st = ctxB + 64;          // 512
    float* f2   = h2st + 512;         // 64
    int*   knS  = (int*)(f2 + 64);    // 256
    int*   stSl = knS + 256;          // 256
    int*   sidS = stSl + 256;         // 8
    unsigned char* colS = (unsigned char*)(sidS + 8);   // 16384B, 16B aligned

    const int g = blockIdx.x, t = threadIdx.x;
    const int base = g * NPG;
    const int w = t >> 5, lane = t & 31;
    const int n = t >> 1, half = t & 1;

    // ---- phase A: stage everything into SMEM --------------------------------
    for (int i = t; i < 2304; i += 512) xs[i] = x[(size_t)base * 9 + i];
    for (int i = t; i < 288;  i += 512) W1s[i] = W1[i];
    for (int i = t; i < 2048; i += 512) W2s[i] = W2[i];
    for (int i = t; i < 4096; i += 512) As[i]  = fc1W[i];
    if (t < 32) b1s[t] = b1[t];
    if (t < 64) { b2s[t] = b2[t]; f2[t] = fc2W[t]; }
    if (t < 8) {
        sidS[t] = g_is64 ? (int)((const long long*)sids)[t]
                         : ((const int*)sids)[t];
    }
    if (t < 256) {
        int c = g_cur[base + t];
        knS[t] = min(c, MAXDEG);
        dv[t] = rsqrtf((float)c + 1.0f);
    }
    {
        uint4* cd = (uint4*)colS;
        const uint4* cg = (const uint4*)(g_col + (size_t)base * MAXDEG);
        for (int i = t; i < 1024; i += 512) cd[i] = cg[i];
    }
    __syncthreads();

    if (t < 256) {
        int sl = -1;
        #pragma unroll
        for (int s = 0; s < 8; s++) if (sidS[s] == t) sl = s;
        stSl[t] = sl;
    }

    // ---- layer 1 linear: p1[i][c] = dinv[i] * (x@W1)[i][c] (p1 aliases p2) --
    {
        float* p1 = p2;
        float a[9];
        #pragma unroll
        for (int k = 0; k < 9; k++) a[k] = xs[n * 9 + k];
        float di = dv[n];
        int cb = half * 16;
        #pragma unroll
        for (int c = 0; c < 16; c += 4) {
            float a0 = 0.f, a1 = 0.f, a2 = 0.f, a3 = 0.f;
            #pragma unroll
            for (int k = 0; k < 9; k++) {
                float4 wv = *(const float4*)&W1s[k * 32 + cb + c];
                a0 += a[k] * wv.x; a1 += a[k] * wv.y;
                a2 += a[k] * wv.z; a3 += a[k] * wv.w;
            }
            p1[n * 33 + cb + c + 0] = di * a0;
            p1[n * 33 + cb + c + 1] = di * a1;
            p1[n * 33 + cb + c + 2] = di * a2;
            p1[n * 33 + cb + c + 3] = di * a3;
        }
    }
    __syncthreads();

    // ---- layer 1 aggregate -> h1 (ReLU) -------------------------------------
    {
        float* p1 = p2;
        for (int nn = w; nn < 256; nn += 16) {
            int kn = knS[nn];
            const unsigned char* cp = colS + nn * MAXDEG;
            float s = 0.f;
            for (int k = 0; k < kn; k++) s += p1[cp[k] * 33 + lane];
            float h = dv[nn] * (s + p1[nn * 33 + lane]) + b1s[lane];
            h1s[nn * 33 + lane] = fmaxf(h, 0.f);
        }
    }
    __syncthreads();

    // ---- layer 2 linear (packed f32x2): p2[i][c] = dinv[i] * (h1@W2)[i][c] --
    {
        unsigned long long acc[16];
        #pragma unroll
        for (int p = 0; p < 16; p++) acc[p] = 0ull;
        const int cb2 = half * 32;
        #pragma unroll
        for (int k = 0; k < 32; k++) {
            unsigned long long ap;
            PACK1(ap, __float_as_uint(h1s[n * 33 + k]));
            const ulonglong2* wr = (const ulonglong2*)&W2s[k * 64 + cb2];
            #pragma unroll
            for (int p = 0; p < 8; p++) {
                ulonglong2 wv = wr[p];
                FMA2(acc[2 * p],     ap, wv.x, acc[2 * p]);
                FMA2(acc[2 * p + 1], ap, wv.y, acc[2 * p + 1]);
            }
        }
        unsigned long long dp;
        PACK1(dp, __float_as_uint(dv[n]));
        #pragma unroll
        for (int p = 0; p < 16; p++) {
            unsigned long long r;
            MUL2(r, acc[p], dp);
            *(unsigned long long*)&p2[n * 66 + cb2 + 2 * p] = r;
        }
    }
    __syncthreads();

    // ---- layer 2 aggregate + ReLU + pool + station rows ---------------------
    {
        const int c0 = 2 * lane;
        float pl0 = 0.f, pl1 = 0.f;
        for (int nn = w; nn < 256; nn += 16) {
            int kn = knS[nn];
            const unsigned char* cp = colS + nn * MAXDEG;
            float s0 = 0.f, s1 = 0.f;
            for (int k = 0; k < kn; k++) {
                float2 v = *(const float2*)&p2[cp[k] * 66 + c0];
                s0 += v.x; s1 += v.y;
            }
            float2 ps = *(const float2*)&p2[nn * 66 + c0];
            float dvn = dv[nn];
            float h0  = fmaxf(dvn * (s0 + ps.x) + b2s[c0],     0.f);
            float h1v = fmaxf(dvn * (s1 + ps.y) + b2s[c0 + 1], 0.f);
            pl0 += h0; pl1 += h1v;
            int sl = stSl[nn];
            if (sl >= 0) { h2st[sl * 64 + c0] = h0; h2st[sl * 64 + c0 + 1] = h1v; }
        }
        pool[w * 64 + c0]     = pl0;
        pool[w * 64 + c0 + 1] = pl1;
    }
    __syncthreads();

    // ---- mean pool reduce ----------------------------------------------------
    if (t < 64) {
        float s = 0.f;
        #pragma unroll
        for (int ww = 0; ww < 16; ww++) s += pool[ww * 64 + t];
        ctx[t] = s * (1.0f / 256.0f);
    }
    __syncthreads();

    // ---- ctxB = ctx @ fc1_W[64:128] + fc1_b ----------------------------------
    if (t < 64) {
        float s = fc1b[t];
        #pragma unroll
        for (int k = 0; k < 64; k++) s += ctx[k] * fc1W[(64 + k) * 64 + t];
        ctxB[t] = s;
    }
    __syncthreads();

    // ---- head: warp per station ----------------------------------------------
    if (w < 8) {
        float e0 = h2st[w * 64 + lane];
        float e1 = h2st[w * 64 + 32 + lane];
        float h0 = ctxB[lane], hb = ctxB[lane + 32];
        #pragma unroll
        for (int k = 0; k < 64; k++) {
            float ek = __shfl_sync(0xffffffffu, (k < 32) ? e0 : e1, k & 31);
            h0 += ek * As[k * 64 + lane];
            hb += ek * As[k * 64 + lane + 32];
        }
        h0 = fmaxf(h0, 0.f); hb = fmaxf(hb, 0.f);
        float q = h0 * f2[lane] + hb * f2[lane + 32];
        #pragma unroll
        for (int off = 16; off; off >>= 1)
            q += __shfl_down_sync(0xffffffffu, q, off);
        if (lane == 0) out[g * 8 + w] = q + fc2b[0];
    }
}

// ---------------------------------------------------------------------------
extern "C" void kernel_launch(void* const* d_in, const int* in_sizes, int n_in,
                              void* d_out, int out_size) {
    // Map inputs by element count. Unique sizes except the three 64-element
    // arrays, which appear in order (b2, fc1_b, fc2_W) under both insertion
    // and alphabetical conventions.
    const float *x = 0, *W1 = 0, *b1 = 0, *W2 = 0, *fc1W = 0, *fc2b = 0;
    const void  *ei = 0, *sids = 0;
    const float *sz64[3] = {0, 0, 0};
    int n64 = 0;
    for (int i = 0; i < n_in; i++) {
        switch (in_sizes[i]) {
            case 2359296: x    = (const float*)d_in[i]; break;
            case 4194304: ei   = d_in[i];               break;
            case 8:       sids = d_in[i];               break;
            case 288:     W1   = (const float*)d_in[i]; break;
            case 32:      b1   = (const float*)d_in[i]; break;
            case 2048:    W2   = (const float*)d_in[i]; break;
            case 8192:    fc1W = (const float*)d_in[i]; break;
            case 1:       fc2b = (const float*)d_in[i]; break;
            case 64:      if (n64 < 3) sz64[n64++] = (const float*)d_in[i]; break;
            default: break;
        }
    }
    const float* b2   = sz64[0];
    const float* fc1b = sz64[1];
    const float* fc2W = sz64[2];
    float* out = (float*)d_out;

    cudaFuncSetAttribute(k_fused, cudaFuncAttributeMaxDynamicSharedMemorySize, SMEM_FUSED);

    k_detect<<<1, 32>>>((const unsigned int*)ei);
    k_zero<<<NN / 256, 256>>>();
    k_fill<<<NE / 256, 256>>>(ei);
    k_fused<<<NG, 512, SMEM_FUSED>>>(x, W1, b1, W2, b2, fc1W, fc1b, fc2W, fc2b, sids, out);
}

// round 5
// speedup vs baseline: 2.2028x; 1.6719x over previous
#include <cuda_runtime.h>

#define NN 262144              // total nodes
#define NE 2097152             // total edges
#define NG 1024                // graphs
#define NPG 256                // nodes per graph
#define MAXDEG 64              // per-node in-edge capacity (avg deg 8)

typedef unsigned long long u64;

// ---------------- scratch (static device memory) ----------------------------
__device__ int            g_is64;
__device__ int            g_cur[NN];                      // in-degree / fill cursor
__device__ unsigned char  g_col[(size_t)NN * MAXDEG];     // 16MB: local src ids

// ---------------- packed f32x2 helpers (Blackwell) --------------------------
#define FMA2(d, a, b, c) asm("fma.rn.f32x2 %0, %1, %2, %3;" : "=l"(d) : "l"(a), "l"(b), "l"(c))
#define ADD2(d, a, b)    asm("add.rn.f32x2 %0, %1, %2;"     : "=l"(d) : "l"(a), "l"(b))
#define PACK1(d, s)      asm("mov.b64 %0, {%1, %1};"        : "=l"(d) : "r"(s))
#define UNPK(lo, hi, v)  asm("mov.b64 {%0, %1}, %2;"        : "=f"(lo), "=f"(hi) : "l"(v))

// ---------------- dtype-agnostic index loads --------------------------------
__device__ __forceinline__ int edge_val(const void* ei, long long idx, int is64) {
    if (is64) return (int)((const long long*)ei)[idx];
    return ((const int*)ei)[idx];
}

// edge_index may be int32 or int64. If int64 (LE), every odd 32-bit word of
// the first 1024 values is 0 (node ids < 2^18); for int32 they are node ids.
__global__ void k_detect(const unsigned int* ei) {
    bool ok = true;
    for (int i = threadIdx.x; i < 1024; i += 32)
        if (ei[2 * i + 1] != 0u) ok = false;
    unsigned m = __ballot_sync(0xffffffffu, ok);
    if (threadIdx.x == 0) g_is64 = (m == 0xffffffffu) ? 1 : 0;
}

__global__ void k_zero() {
    int i = blockIdx.x * blockDim.x + threadIdx.x;
    if (i < NN) g_cur[i] = 0;
}

// single pass: build capped CSR; g_cur ends as the exact in-degree
__global__ void k_fill(const void* ei) {
    int e = blockIdx.x * blockDim.x + threadIdx.x;
    if (e < NE) {
        int is64 = g_is64;
        int s = edge_val(ei, e, is64);
        int d = edge_val(ei, (long long)NE + e, is64);
        int pos = atomicAdd(&g_cur[d], 1);
        if (pos < MAXDEG)
            g_col[(size_t)d * MAXDEG + pos] = (unsigned char)(s & 255);
    }
}

// ---------------- fully fused per-graph network ------------------------------
// block = one graph, 256 threads (thread-per-node), 2 blocks/SM.
// Aggregate-first identity: out_i = dinv_i * ((sum_s dinv_s h_s + dinv_i h_i) @ W) + b.
// SMEM overlay plan in R[18432]:
//   xd  [256x12] @ R+0      -> dead after L1 agg sync
//   q1  [256x12] @ R+9216   -> dead after L1 linear
//   h1d [256x36] @ R+0      (exactly [0,9216))
//   q2  [256x36] @ R+9216   ([9216,18432))
//   h2  [256x68] @ R+0      ([0,17408)) -- overlays q2 only after acc2 in regs
#define R_SZ     18432
#define SMEM_FUSED ((R_SZ + 2048 + 4096 + 288 + 32 + 64 + 64 + 64 + 64 + 64 + 512 + 256 + 256 + 8) * 4)

extern __shared__ float sm[];
__global__ void __launch_bounds__(256, 2) k_fused(
    const float* __restrict__ x,    const float* __restrict__ W1,
    const float* __restrict__ b1,   const float* __restrict__ W2,
    const float* __restrict__ b2,   const float* __restrict__ fc1W,
    const float* __restrict__ fc1b, const float* __restrict__ fc2W,
    const float* __restrict__ fc2b, const void*  __restrict__ sids,
    float* __restrict__ out)
{
    float* R     = sm;
    float* W2s   = R + R_SZ;          // 2048
    float* As    = W2s + 2048;        // 4096
    float* W1s   = As + 4096;         // 288
    float* b1s   = W1s + 288;         // 32
    float* b2s   = b1s + 32;          // 64
    float* f2    = b2s + 64;          // 64
    float* fc1bS = f2 + 64;           // 64
    float* ctx   = fc1bS + 64;        // 64
    float* ctxB  = ctx + 64;          // 64
    float* pool  = ctxB + 64;         // 512 (8 groups x 64)
    float* dv    = pool + 512;        // 256
    int*   knS   = (int*)(dv + 256);  // 256
    int*   sidS  = knS + 256;         // 8

    float* xd  = R;                   // 256x12
    float* q1  = R + 9216;            // 256x12
    float* h1d = R;                   // 256x36
    float* q2  = R + 9216;            // 256x36
    float* h2  = R;                   // 256x68

    const int g = blockIdx.x, t = threadIdx.x;      // t == local node id
    const int base = g * NPG;
    const int w = t >> 5, lane = t & 31;

    // ---- phase A: degrees + weights + x*dinv -------------------------------
    int   cnt = g_cur[base + t];
    float dvn = rsqrtf((float)cnt + 1.0f);
    knS[t] = min(cnt, MAXDEG);
    dv[t]  = dvn;
    {   // x row for this node, scaled by dinv
        const float* xr = x + (size_t)(base + t) * 9;
        #pragma unroll
        for (int c = 0; c < 9; c++) xd[t * 12 + c] = xr[c] * dvn;
    }
    for (int i = t; i < 288;  i += 256) W1s[i] = W1[i];
    {   const float4* s4 = (const float4*)W2;  float4* d4 = (float4*)W2s;
        for (int i = t; i < 512; i += 256) d4[i] = s4[i]; }
    {   const float4* s4 = (const float4*)fc1W; float4* d4 = (float4*)As;
        for (int i = t; i < 1024; i += 256) d4[i] = s4[i]; }
    if (t < 32) b1s[t] = b1[t];
    if (t < 64) { b2s[t] = b2[t]; f2[t] = fc2W[t]; fc1bS[t] = fc1b[t]; }
    if (t < 8)  sidS[t] = g_is64 ? (int)((const long long*)sids)[t]
                                 : ((const int*)sids)[t];
    __syncthreads();

    const u64* cp = (const u64*)(g_col + (size_t)(base + t) * MAXDEG);
    const int  kn = knS[t];

    // ---- L1 aggregate (9-dim): q1[n] = sum_src xd[src] + xd[n] -------------
    {
        float4 a03 = *(const float4*)&xd[t * 12];
        float4 a47 = *(const float4*)&xd[t * 12 + 4];
        float  a8  = xd[t * 12 + 8];
        for (int ch = 0; ch * 8 < kn; ch++) {
            u64 v = cp[ch];
            int lim = min(8, kn - ch * 8);
            for (int b = 0; b < lim; b++) {
                int j = (int)(v & 255u); v >>= 8;
                float4 s03 = *(const float4*)&xd[j * 12];
                float4 s47 = *(const float4*)&xd[j * 12 + 4];
                a03.x += s03.x; a03.y += s03.y; a03.z += s03.z; a03.w += s03.w;
                a47.x += s47.x; a47.y += s47.y; a47.z += s47.z; a47.w += s47.w;
                a8 += xd[j * 12 + 8];
            }
        }
        *(float4*)&q1[t * 12]     = a03;
        *(float4*)&q1[t * 12 + 4] = a47;
        q1[t * 12 + 8] = a8;
    }
    __syncthreads();   // all xd reads done -> h1d may overlay xd

    // ---- L1 linear 9->32: h1d[n] = dinv*relu(dinv*(q1@W1) + b1) ------------
    {
        float a[9];
        #pragma unroll
        for (int k = 0; k < 9; k++) a[k] = q1[t * 12 + k];
        u64 acc[16];                 // acc[j] holds channels (2j, 2j+1)
        #pragma unroll
        for (int p = 0; p < 16; p++) acc[p] = 0ull;
        #pragma unroll
        for (int k = 0; k < 9; k++) {
            u64 ap; PACK1(ap, __float_as_uint(a[k]));
            const ulonglong2* wr = (const ulonglong2*)&W1s[k * 32];   // 8 u2 per row
            #pragma unroll
            for (int p = 0; p < 8; p++) {
                ulonglong2 wv = wr[p];
                FMA2(acc[2 * p],     ap, wv.x, acc[2 * p]);        // ch 4p,4p+1
                FMA2(acc[2 * p + 1], ap, wv.y, acc[2 * p + 1]);    // ch 4p+2,4p+3
            }
        }
        #pragma unroll
        for (int p = 0; p < 16; p++) {
            float lo, hi; UNPK(lo, hi, acc[p]);
            float2 o;
            o.x = fmaxf(fmaf(dvn, lo, b1s[2 * p]),     0.f) * dvn;
            o.y = fmaxf(fmaf(dvn, hi, b1s[2 * p + 1]), 0.f) * dvn;
            *(float2*)&h1d[t * 36 + 2 * p] = o;
        }
    }
    __syncthreads();   // all h1d rows visible

    // ---- L2 aggregate (32-dim): q2[n] = sum_src h1d[src] + h1d[n] ----------
    {
        u64 acc[16];
        {
            const ulonglong2* sr = (const ulonglong2*)&h1d[t * 36];
            #pragma unroll
            for (int p = 0; p < 8; p++) {
                ulonglong2 sv = sr[p];
                acc[2 * p] = sv.x; acc[2 * p + 1] = sv.y;
            }
        }
        for (int ch = 0; ch * 8 < kn; ch++) {
            u64 v = cp[ch];
            int lim = min(8, kn - ch * 8);
            for (int b = 0; b < lim; b++) {
                int j = (int)(v & 255u); v >>= 8;
                const ulonglong2* sr = (const ulonglong2*)&h1d[j * 36];
                #pragma unroll
                for (int p = 0; p < 8; p++) {
                    ulonglong2 sv = sr[p];
                    ADD2(acc[2 * p],     acc[2 * p],     sv.x);
                    ADD2(acc[2 * p + 1], acc[2 * p + 1], sv.y);
                }
            }
        }
        ulonglong2* qr = (ulonglong2*)&q2[t * 36];
        #pragma unroll
        for (int p = 0; p < 8; p++) {
            ulonglong2 o; o.x = acc[2 * p]; o.y = acc[2 * p + 1];
            qr[p] = o;
        }
    }
    // no sync needed: L2 linear reads only this thread's own q2 row

    // ---- L2 linear 32->64: h2[n] = relu(dinv*(q2@W2) + b2) (regs) ----------
    // acc2[j] holds output channels (2j, 2j+1); W2 row = 64 floats = 16 u2.
    u64 acc2[32];
    {
        #pragma unroll
        for (int p = 0; p < 32; p++) acc2[p] = 0ull;
        const ulonglong2* w2v = (const ulonglong2*)W2s;
        #pragma unroll
        for (int kq = 0; kq < 8; kq++) {
            float4 a4 = *(const float4*)&q2[t * 36 + kq * 4];
            float av[4] = {a4.x, a4.y, a4.z, a4.w};
            #pragma unroll
            for (int kk = 0; kk < 4; kk++) {
                int k = kq * 4 + kk;
                u64 ap; PACK1(ap, __float_as_uint(av[kk]));
                const ulonglong2* wr = w2v + k * 16;      // FIXED: 16 u2 per row
                #pragma unroll
                for (int p = 0; p < 16; p++) {            // FIXED: full row
                    ulonglong2 wv = wr[p];
                    FMA2(acc2[2 * p],     ap, wv.x, acc2[2 * p]);
                    FMA2(acc2[2 * p + 1], ap, wv.y, acc2[2 * p + 1]);
                }
            }
        }
    }
    __syncthreads();   // all q2/h1d reads done -> safe to overlay h2

    {
        #pragma unroll
        for (int p = 0; p < 32; p++) {
            float lo, hi; UNPK(lo, hi, acc2[p]);
            float2 o;
            o.x = fmaxf(fmaf(dvn, lo, b2s[2 * p]),     0.f);
            o.y = fmaxf(fmaf(dvn, hi, b2s[2 * p + 1]), 0.f);
            *(float2*)&h2[t * 68 + 2 * p] = o;
        }
    }
    __syncthreads();

    // ---- mean pool: ctx = mean over nodes of h2 ----------------------------
    {
        int c2 = (t & 31) * 2, grp = t >> 5;   // 8 groups x 32 rows each
        float s0 = 0.f, s1 = 0.f;
        for (int i = 0; i < 32; i++) {
            int r = grp + 8 * i;
            float2 v = *(const float2*)&h2[r * 68 + c2];
            s0 += v.x; s1 += v.y;
        }
        pool[grp * 64 + c2]     = s0;
        pool[grp * 64 + c2 + 1] = s1;
    }
    __syncthreads();
    if (t < 64) {
        float s = 0.f;
        #pragma unroll
        for (int gg = 0; gg < 8; gg++) s += pool[gg * 64 + t];
        ctx[t] = s * (1.0f / 256.0f);
    }
    __syncthreads();

    // ---- ctxB = ctx @ fc1_W[64:128] + fc1_b (global weight reads, L2-hot) --
    if (t < 64) {
        float s = fc1bS[t];
        #pragma unroll
        for (int k = 0; k < 64; k++) s += ctx[k] * __ldg(&fc1W[(64 + k) * 64 + t]);
        ctxB[t] = s;
    }
    __syncthreads();

    // ---- head: warp per station ---------------------------------------------
    {
        int node = sidS[w];
        float e0 = h2[node * 68 + lane];
        float e1 = h2[node * 68 + 32 + lane];
        float h0 = ctxB[lane], hb = ctxB[lane + 32];
        #pragma unroll
        for (int k = 0; k < 64; k++) {
            float ek = __shfl_sync(0xffffffffu, (k < 32) ? e0 : e1, k & 31);
            h0 += ek * As[k * 64 + lane];
            hb += ek * As[k * 64 + lane + 32];
        }
        h0 = fmaxf(h0, 0.f); hb = fmaxf(hb, 0.f);
        float q = h0 * f2[lane] + hb * f2[lane + 32];
        #pragma unroll
        for (int off = 16; off; off >>= 1)
            q += __shfl_down_sync(0xffffffffu, q, off);
        if (lane == 0) out[g * 8 + w] = q + fc2b[0];
    }
}

// ---------------------------------------------------------------------------
extern "C" void kernel_launch(void* const* d_in, const int* in_sizes, int n_in,
                              void* d_out, int out_size) {
    // Map inputs by element count. Unique sizes except the three 64-element
    // arrays, which appear in order (b2, fc1_b, fc2_W) under both insertion
    // and alphabetical conventions.
    const float *x = 0, *W1 = 0, *b1 = 0, *W2 = 0, *fc1W = 0, *fc2b = 0;
    const void  *ei = 0, *sids = 0;
    const float *sz64[3] = {0, 0, 0};
    int n64 = 0;
    for (int i = 0; i < n_in; i++) {
        switch (in_sizes[i]) {
            case 2359296: x    = (const float*)d_in[i]; break;
            case 4194304: ei   = d_in[i];               break;
            case 8:       sids = d_in[i];               break;
            case 288:     W1   = (const float*)d_in[i]; break;
            case 32:      b1   = (const float*)d_in[i]; break;
            case 2048:    W2   = (const float*)d_in[i]; break;
            case 8192:    fc1W = (const float*)d_in[i]; break;
            case 1:       fc2b = (const float*)d_in[i]; break;
            case 64:      if (n64 < 3) sz64[n64++] = (const float*)d_in[i]; break;
            default: break;
        }
    }
    const float* b2   = sz64[0];
    const float* fc1b = sz64[1];
    const float* fc2W = sz64[2];
    float* out = (float*)d_out;

    cudaFuncSetAttribute(k_fused, cudaFuncAttributeMaxDynamicSharedMemorySize, SMEM_FUSED);

    k_detect<<<1, 32>>>((const unsigned int*)ei);
    k_zero<<<NN / 256, 256>>>();
    k_fill<<<NE / 256, 256>>>(ei);
    k_fused<<<NG, 256, SMEM_FUSED>>>(x, W1, b1, W2, b2, fc1W, fc1b, fc2W, fc2b, sids, out);
}